// round 11
// baseline (speedup 1.0000x reference)
#include <cuda_runtime.h>
#include <cuda_fp16.h>
#include <mma.h>
using namespace nvcuda;

#define MAXN 50000
#define NPAD 50048          // padded rows so 128-row GEMM tiles store unguarded
#define MAXE 800000
#define DIM 128

// ---------------- scratch (allocation-free) ----------------
__device__ uint2  g_xh[NPAD * 32];   // half4: x in fp16 (GEMM1 A)
__device__ uint2  g_h1[NPAD * 32];   // half4: GEMM1 out (GAT1 gather input)
__device__ uint2  g_h2[NPAD * 32];   // half4: GAT1 out (GEMM2 A)
__device__ uint2  g_h3[NPAD * 32];   // half4: GEMM2 out (GAT2 gather input)
__device__ uint2  g_h4[MAXN * 32];   // half4: GAT2 out (mean-conv input)
__device__ __half g_W1h[DIM * DIM];
__device__ __half g_W2h[DIM * DIM];
__device__ float  g_val[768];        // v1s(2x128), v1d(2x128), u2s(128), u2d(128)
__device__ float g_as1[MAXN * 2];
__device__ float g_ad1[MAXN * 2];
__device__ float g_as2[MAXN];
__device__ float g_ad2[MAXN];
__device__ int g_rank[MAXE];
__device__ int g_csrc[MAXE];
__device__ int g_rowptr[MAXN + 1];
__device__ int g_cnt[MAXN];
__device__ int g_is64;

// ---------------- helpers ----------------
__device__ __forceinline__ float4 h4f4(uint2 u) {
    half2 a = *reinterpret_cast<half2*>(&u.x);
    half2 b = *reinterpret_cast<half2*>(&u.y);
    float2 fa = __half22float2(a), fb = __half22float2(b);
    float4 r; r.x = fa.x; r.y = fa.y; r.z = fb.x; r.w = fb.y; return r;
}
__device__ __forceinline__ uint2 f4h4(float4 v) {
    half2 a = __floats2half2_rn(v.x, v.y);
    half2 b = __floats2half2_rn(v.z, v.w);
    uint2 u;
    u.x = *reinterpret_cast<unsigned*>(&a);
    u.y = *reinterpret_cast<unsigned*>(&b);
    return u;
}
__device__ __forceinline__ float dot4(float4 a, float4 b) {
    return a.x * b.x + a.y * b.y + a.z * b.z + a.w * b.w;
}

// ---------------- dtype sniff (R7 form) ----------------
__global__ void detect_kernel(const unsigned int* __restrict__ raw, int E) {
    if (threadIdx.x != 0 || blockIdx.x != 0) return;
    int step = E / 64; if (step < 1) step = 1;
    int allz = 1;
    for (int k = 0; k < 64; k++) {
        long long j = 2LL * (long long)k * step + 1;
        if (j >= 2LL * E) break;
        if (raw[j] != 0u) { allz = 0; break; }
    }
    g_is64 = allz;
}

// ---------------- histogram + per-edge rank (8 edges/thread) ----------------
__global__ void convert_idx_kernel(const void* __restrict__ raw, int* __restrict__ rank,
                                   int* __restrict__ cnt, int E) {
    int i0 = (blockIdx.x * blockDim.x + threadIdx.x) * 8;
    if (i0 >= E) return;
    int m = min(8, E - i0);
    int dv[8];
    if (g_is64) {
        const int2* p = (const int2*)raw;
        #pragma unroll
        for (int k = 0; k < 8; k++) if (k < m) dv[k] = p[E + i0 + k].x;
    } else {
        const int* p = (const int*)raw;
        #pragma unroll
        for (int k = 0; k < 8; k++) if (k < m) dv[k] = p[E + i0 + k];
    }
    #pragma unroll
    for (int k = 0; k < 8; k++) if (k < m) rank[i0 + k] = atomicAdd(&cnt[dv[k]], 1);
}

// ---------------- single-block exclusive scan ----------------
__global__ void scan_kernel(const int* __restrict__ cnt, int* __restrict__ rowptr, int n) {
    __shared__ int part[1024];
    int t = threadIdx.x;
    int chunk = (n + 1023) >> 10;
    int b = t * chunk, e = min(b + chunk, n);
    int s = 0;
    for (int i = b; i < e; i++) s += cnt[i];
    part[t] = s;
    __syncthreads();
    #pragma unroll
    for (int off = 1; off < 1024; off <<= 1) {
        int v = (t >= off) ? part[t - off] : 0;
        __syncthreads();
        part[t] += v;
        __syncthreads();
    }
    int base = (t > 0) ? part[t - 1] : 0;
    for (int i = b; i < e; i++) { rowptr[i] = base; base += cnt[i]; }
    if (t == 1023) rowptr[n] = part[1023];
}

// ---------------- CSR fill: pure scatter, 8 edges/thread ----------------
__global__ void fill_kernel(const void* __restrict__ raw, const int* __restrict__ rank,
                            const int* __restrict__ rowptr, int* __restrict__ csrc, int E) {
    int i0 = (blockIdx.x * blockDim.x + threadIdx.x) * 8;
    if (i0 >= E) return;
    int m = min(8, E - i0);
    int sv[8], dv[8], rv[8], rp[8];
    if (g_is64) {
        const int2* p = (const int2*)raw;
        #pragma unroll
        for (int k = 0; k < 8; k++) if (k < m) { sv[k] = p[i0 + k].x; dv[k] = p[E + i0 + k].x; }
    } else {
        const int* p = (const int*)raw;
        #pragma unroll
        for (int k = 0; k < 8; k++) if (k < m) { sv[k] = p[i0 + k]; dv[k] = p[E + i0 + k]; }
    }
    #pragma unroll
    for (int k = 0; k < 8; k++) if (k < m) rv[k] = rank[i0 + k];
    #pragma unroll
    for (int k = 0; k < 8; k++) if (k < m) rp[k] = rowptr[dv[k]];
    #pragma unroll
    for (int k = 0; k < 8; k++) if (k < m) csrc[rp[k] + rv[k]] = sv[k];
}

// ---------------- prep: W -> fp16, fused logit vectors v = W^T a ----------------
__global__ void prep_kernel(const float* __restrict__ W1, const float* __restrict__ W2,
                            const float* __restrict__ a1s, const float* __restrict__ a1d,
                            const float* __restrict__ a2s, const float* __restrict__ a2d,
                            __half* __restrict__ W1h, __half* __restrict__ W2h,
                            float* __restrict__ val) {
    int t = threadIdx.x;
    for (int i = t; i < DIM * DIM; i += 256) {
        W1h[i] = __float2half(W1[i]);
        W2h[i] = __float2half(W2[i]);
    }
    if (t < 128) {
        int k = t;
        float s0 = 0.f, s1 = 0.f, d0 = 0.f, d1 = 0.f;
        for (int c = 0; c < 64; c++) {
            float w0 = W1[c * DIM + k], w1 = W1[(64 + c) * DIM + k];
            s0 += a1s[c] * w0;      s1 += a1s[64 + c] * w1;
            d0 += a1d[c] * w0;      d1 += a1d[64 + c] * w1;
        }
        val[k] = s0; val[128 + k] = s1; val[256 + k] = d0; val[384 + k] = d1;
        float us = 0.f, ud = 0.f;
        for (int o = 0; o < 128; o++) {
            float w = W2[o * DIM + k];
            us += a2s[o] * w; ud += a2d[o] * w;
        }
        val[512 + k] = us; val[640 + k] = ud;
    }
}

// ---------------- x -> fp16 + layer-1 logits (exact fp32 math) ----------------
__global__ void xconv_kernel(const float4* __restrict__ x, const float* __restrict__ val,
                             uint2* __restrict__ xh, float* __restrict__ as1,
                             float* __restrict__ ad1, int n) {
    int g = blockIdx.x * blockDim.x + threadIdx.x;
    int node = g >> 5, lane = g & 31;
    if (node >= n) return;
    float4 xv = x[node * 32 + lane];
    xh[node * 32 + lane] = f4h4(xv);
    float4 vs0 = ((const float4*)val)[lane];
    float4 vs1 = ((const float4*)(val + 128))[lane];
    float4 vd0 = ((const float4*)(val + 256))[lane];
    float4 vd1 = ((const float4*)(val + 384))[lane];
    float s0 = dot4(xv, vs0), s1 = dot4(xv, vs1);
    float d0 = dot4(xv, vd0), d1 = dot4(xv, vd1);
    #pragma unroll
    for (int off = 16; off >= 1; off >>= 1) {
        s0 += __shfl_xor_sync(0xffffffff, s0, off);
        s1 += __shfl_xor_sync(0xffffffff, s1, off);
        d0 += __shfl_xor_sync(0xffffffff, d0, off);
        d1 += __shfl_xor_sync(0xffffffff, d1, off);
    }
    if (lane == 0) {
        as1[node * 2] = s0; as1[node * 2 + 1] = s1;
        ad1[node * 2] = d0; ad1[node * 2 + 1] = d1;
    }
}

// ---------------- fp16 WMMA GEMM: C[m][o] = sum_k A[m][k] * W[o][k] ----------------
__global__ void hgemm_kernel(const __half* __restrict__ A, const __half* __restrict__ W,
                             __half* __restrict__ C, int nrows) {
    extern __shared__ __half smh[];
    __half* As = smh;              // [128][136]
    __half* Bs = smh + 128 * 136;  // [128][136]
    int tid = threadIdx.x;
    int row0 = blockIdx.x * 128;

    #pragma unroll
    for (int i = 0; i < 16; i++) {
        int idx = tid + i * 256;
        int r = idx >> 5, c4 = idx & 31;
        uint2 v = {0u, 0u};
        if (row0 + r < nrows) v = ((const uint2*)A)[(size_t)(row0 + r) * 32 + c4];
        *(uint2*)&As[r * 136 + c4 * 4] = v;
    }
    #pragma unroll
    for (int i = 0; i < 16; i++) {
        int idx = tid + i * 256;
        int r = idx >> 5, c4 = idx & 31;
        *(uint2*)&Bs[r * 136 + c4 * 4] = ((const uint2*)W)[idx];
    }
    __syncthreads();

    int wid = tid >> 5;
    int wm = wid >> 1, wn = wid & 1;

    wmma::fragment<wmma::accumulator, 16, 16, 16, float> acc[2][4];
    #pragma unroll
    for (int i = 0; i < 2; i++)
        #pragma unroll
        for (int j = 0; j < 4; j++) wmma::fill_fragment(acc[i][j], 0.f);

    #pragma unroll
    for (int ks = 0; ks < 8; ks++) {
        wmma::fragment<wmma::matrix_a, 16, 16, 16, __half, wmma::row_major> af[2];
        #pragma unroll
        for (int i = 0; i < 2; i++)
            wmma::load_matrix_sync(af[i], &As[(wm * 32 + i * 16) * 136 + ks * 16], 136);
        wmma::fragment<wmma::matrix_b, 16, 16, 16, __half, wmma::col_major> bf[4];
        #pragma unroll
        for (int j = 0; j < 4; j++)
            wmma::load_matrix_sync(bf[j], &Bs[(wn * 64 + j * 16) * 136 + ks * 16], 136);
        #pragma unroll
        for (int i = 0; i < 2; i++)
            #pragma unroll
            for (int j = 0; j < 4; j++)
                wmma::mma_sync(acc[i][j], af[i], bf[j], acc[i][j]);
    }

    #pragma unroll
    for (int i = 0; i < 2; i++)
        #pragma unroll
        for (int j = 0; j < 4; j++) {
            wmma::fragment<wmma::accumulator, 16, 16, 16, __half> hf;
            #pragma unroll
            for (int e = 0; e < hf.num_elements; e++) hf.x[e] = __float2half(acc[i][j].x[e]);
            wmma::store_matrix_sync(&C[(size_t)(row0 + wm * 32 + i * 16) * DIM + wn * 64 + j * 16],
                                    hf, DIM, wmma::mem_row_major);
        }
}

// ---------------- GAT gather (R7 winner shape): warp/dst node, x8 batched loads ----------------
template <int HEADS, bool RELU, bool ALPHA2>
__global__ void __launch_bounds__(256)
gat_gather_kernel(const int* __restrict__ rowptr, const int* __restrict__ csrc,
                  const uint2* __restrict__ h, const float* __restrict__ as_,
                  const float* __restrict__ ad_, const float* __restrict__ bias,
                  const float* __restrict__ val, uint2* __restrict__ outh,
                  float* __restrict__ as2, float* __restrict__ ad2, int n) {
    int g = blockIdx.x * blockDim.x + threadIdx.x;
    int d = g >> 5, lane = threadIdx.x & 31;
    if (d >= n) return;
    int head = (HEADS == 2) ? (lane >> 4) : 0;
    float adv = ad_[d * HEADS + head];

    float4 acc;
    float den;
    {   // self loop
        float a = as_[d * HEADS + head] + adv;
        float lr = (a > 0.f) ? a : 0.2f * a;
        float w = __expf(lr);
        float4 hv = h4f4(h[d * 32 + lane]);
        acc.x = w * hv.x; acc.y = w * hv.y; acc.z = w * hv.z; acc.w = w * hv.w;
        den = w;
    }

    int e0 = rowptr[d], e1 = rowptr[d + 1];
    int e = e0;
    for (; e + 8 <= e1; e += 8) {
        int s[8];
        #pragma unroll
        for (int k = 0; k < 8; k++) s[k] = csrc[e + k];
        float a[8];
        #pragma unroll
        for (int k = 0; k < 8; k++) a[k] = as_[s[k] * HEADS + head];
        uint2 u[8];
        #pragma unroll
        for (int k = 0; k < 8; k++) u[k] = h[s[k] * 32 + lane];
        #pragma unroll
        for (int k = 0; k < 8; k++) {
            float t = a[k] + adv;
            t = (t > 0.f) ? t : 0.2f * t;
            float w = __expf(t);
            float4 hv = h4f4(u[k]);
            acc.x += w * hv.x; acc.y += w * hv.y;
            acc.z += w * hv.z; acc.w += w * hv.w;
            den += w;
        }
    }
    for (; e < e1; e++) {
        int s = csrc[e];
        float a = as_[s * HEADS + head] + adv;
        float lr = (a > 0.f) ? a : 0.2f * a;
        float w = __expf(lr);
        float4 hv = h4f4(h[s * 32 + lane]);
        acc.x += w * hv.x; acc.y += w * hv.y; acc.z += w * hv.z; acc.w += w * hv.w;
        den += w;
    }

    float inv = 1.f / den;
    float4 b = ((const float4*)bias)[lane];
    float4 r;
    r.x = acc.x * inv + b.x; r.y = acc.y * inv + b.y;
    r.z = acc.z * inv + b.z; r.w = acc.w * inv + b.w;
    if (RELU) {
        r.x = fmaxf(r.x, 0.f); r.y = fmaxf(r.y, 0.f);
        r.z = fmaxf(r.z, 0.f); r.w = fmaxf(r.w, 0.f);
    }
    outh[d * 32 + lane] = f4h4(r);

    if (ALPHA2) {
        float4 us = ((const float4*)(val + 512))[lane];
        float4 ud = ((const float4*)(val + 640))[lane];
        float ss = dot4(r, us), dd = dot4(r, ud);
        #pragma unroll
        for (int off = 16; off >= 1; off >>= 1) {
            ss += __shfl_xor_sync(0xffffffff, ss, off);
            dd += __shfl_xor_sync(0xffffffff, dd, off);
        }
        if (lane == 0) { as2[d] = ss; ad2[d] = dd; }
    }
}

// ---------------- mean conv gather (R7 shape) + residual + relu ----------------
__global__ void __launch_bounds__(256)
mean_gather_kernel(const int* __restrict__ rowptr, const int* __restrict__ csrc,
                   const uint2* __restrict__ h, const float4* __restrict__ x,
                   float4* __restrict__ out, int n) {
    int g = blockIdx.x * blockDim.x + threadIdx.x;
    int d = g >> 5, lane = threadIdx.x & 31;
    if (d >= n) return;
    int e0 = rowptr[d], e1 = rowptr[d + 1];
    float4 acc = {0.f, 0.f, 0.f, 0.f};
    int e = e0;
    for (; e + 8 <= e1; e += 8) {
        int s[8];
        #pragma unroll
        for (int k = 0; k < 8; k++) s[k] = csrc[e + k];
        uint2 u[8];
        #pragma unroll
        for (int k = 0; k < 8; k++) u[k] = h[s[k] * 32 + lane];
        #pragma unroll
        for (int k = 0; k < 8; k++) {
            float4 hv = h4f4(u[k]);
            acc.x += hv.x; acc.y += hv.y; acc.z += hv.z; acc.w += hv.w;
        }
    }
    for (; e < e1; e++) {
        float4 hv = h4f4(h[csrc[e] * 32 + lane]);
        acc.x += hv.x; acc.y += hv.y; acc.z += hv.z; acc.w += hv.w;
    }
    int cnt = e1 - e0;
    float inv = (cnt > 0) ? (1.f / (float)cnt) : 0.f;
    float4 xv = x[d * 32 + lane];
    float4 r;
    r.x = fmaxf(acc.x * inv + xv.x, 0.f);
    r.y = fmaxf(acc.y * inv + xv.y, 0.f);
    r.z = fmaxf(acc.z * inv + xv.z, 0.f);
    r.w = fmaxf(acc.w * inv + xv.w, 0.f);
    out[d * 32 + lane] = r;
}

// ---------------- launch ----------------
extern "C" void kernel_launch(void* const* d_in, const int* in_sizes, int n_in,
                              void* d_out, int out_size) {
    const float* x    = (const float*)d_in[0];
    const void*  ei   = d_in[1];
    const float* W1   = (const float*)d_in[2];
    const float* asv1 = (const float*)d_in[3];
    const float* adv1 = (const float*)d_in[4];
    const float* b1   = (const float*)d_in[5];
    const float* W2   = (const float*)d_in[6];
    const float* asv2 = (const float*)d_in[7];
    const float* adv2 = (const float*)d_in[8];
    const float* b2   = (const float*)d_in[9];
    float* out = (float*)d_out;

    int n = in_sizes[0] / DIM;
    int E = in_sizes[1] / 2;

    uint2 *xh, *h1, *h2, *h3, *h4;
    __half *W1h, *W2h;
    float *val, *as1, *ad1, *as2, *ad2;
    int *rank, *csrc, *rowptr, *cnt;
    cudaGetSymbolAddress((void**)&xh,     g_xh);
    cudaGetSymbolAddress((void**)&h1,     g_h1);
    cudaGetSymbolAddress((void**)&h2,     g_h2);
    cudaGetSymbolAddress((void**)&h3,     g_h3);
    cudaGetSymbolAddress((void**)&h4,     g_h4);
    cudaGetSymbolAddress((void**)&W1h,    g_W1h);
    cudaGetSymbolAddress((void**)&W2h,    g_W2h);
    cudaGetSymbolAddress((void**)&val,    g_val);
    cudaGetSymbolAddress((void**)&as1,    g_as1);
    cudaGetSymbolAddress((void**)&ad1,    g_ad1);
    cudaGetSymbolAddress((void**)&as2,    g_as2);
    cudaGetSymbolAddress((void**)&ad2,    g_ad2);
    cudaGetSymbolAddress((void**)&rank,   g_rank);
    cudaGetSymbolAddress((void**)&csrc,   g_csrc);
    cudaGetSymbolAddress((void**)&rowptr, g_rowptr);
    cudaGetSymbolAddress((void**)&cnt,    g_cnt);

    const int hgemm_smem = 2 * 128 * 136 * (int)sizeof(__half);
    cudaFuncSetAttribute(hgemm_kernel, cudaFuncAttributeMaxDynamicSharedMemorySize, hgemm_smem);

    int gemm_blocks  = (n + 127) / 128;
    int nwarp_blocks = (n * 32 + 255) / 256;
    int e8_blocks    = ((E + 7) / 8 + 255) / 256;

    // ---- fork: prep + CSR build on side stream, feature path on main stream ----
    cudaStream_t s;
    cudaStreamCreateWithFlags(&s, cudaStreamNonBlocking);
    cudaEvent_t evFork, evVal, evJoin;
    cudaEventCreateWithFlags(&evFork, cudaEventDisableTiming);
    cudaEventCreateWithFlags(&evVal,  cudaEventDisableTiming);
    cudaEventCreateWithFlags(&evJoin, cudaEventDisableTiming);

    cudaEventRecord(evFork, 0);
    cudaStreamWaitEvent(s, evFork, 0);

    // side stream: prep first (gates xconv/hgemm1), then CSR build
    prep_kernel<<<1, 256, 0, s>>>(W1, W2, asv1, adv1, asv2, adv2, W1h, W2h, val);
    cudaEventRecord(evVal, s);
    cudaMemsetAsync(cnt, 0, (size_t)n * sizeof(int), s);
    detect_kernel<<<1, 64, 0, s>>>((const unsigned int*)ei, E);
    convert_idx_kernel<<<e8_blocks, 256, 0, s>>>(ei, rank, cnt, E);
    scan_kernel<<<1, 1024, 0, s>>>(cnt, rowptr, n);
    fill_kernel<<<e8_blocks, 256, 0, s>>>(ei, rank, rowptr, csrc, E);
    cudaEventRecord(evJoin, s);

    // main stream: x conversion (needs val) + GEMM1 (needs W1h)
    cudaStreamWaitEvent(0, evVal, 0);
    xconv_kernel<<<nwarp_blocks, 256>>>((const float4*)x, val, xh, as1, ad1, n);
    hgemm_kernel<<<gemm_blocks, 256, hgemm_smem>>>((const __half*)xh, W1h, (__half*)h1, n);

    // join: gather-1 needs both CSR and h1
    cudaStreamWaitEvent(0, evJoin, 0);

    gat_gather_kernel<2, true, true><<<nwarp_blocks, 256>>>(rowptr, csrc, h1, as1, ad1, b1,
                                                            val, h2, as2, ad2, n);

    hgemm_kernel<<<gemm_blocks, 256, hgemm_smem>>>((const __half*)h2, W2h, (__half*)h3, n);
    gat_gather_kernel<1, false, false><<<nwarp_blocks, 256>>>(rowptr, csrc, h3, as2, ad2, b2,
                                                              val, h4, nullptr, nullptr, n);

    mean_gather_kernel<<<nwarp_blocks, 256>>>(rowptr, csrc, h4, (const float4*)x,
                                              (float4*)out, n);
    // note: stream/events intentionally not destroyed during potential capture
}

// round 12
// speedup vs baseline: 1.4643x; 1.4643x over previous
#include <cuda_runtime.h>
#include <cuda_fp16.h>
#include <mma.h>
using namespace nvcuda;

#define MAXN 50000
#define NPAD 50048          // padded rows so 128-row GEMM tiles store unguarded
#define MAXE 800000
#define DIM 128

// ---------------- scratch (allocation-free) ----------------
__device__ uint2  g_xh[NPAD * 32];   // half4: x in fp16 (GEMM1 A)
__device__ uint2  g_h1[NPAD * 32];   // half4: GEMM1 out (GAT1 gather input)
__device__ uint2  g_h2[NPAD * 32];   // half4: GAT1 out (GEMM2 A)
__device__ uint2  g_h3[NPAD * 32];   // half4: GEMM2 out (GAT2 gather input)
__device__ uint2  g_h4[MAXN * 32];   // half4: GAT2 out (mean-conv input)
__device__ __half g_W1h[DIM * DIM];
__device__ __half g_W2h[DIM * DIM];
__device__ float  g_val[768];        // v1s(2x128), v1d(2x128), u2s(128), u2d(128)
__device__ float g_as1[MAXN * 2];
__device__ float g_ad1[MAXN * 2];
__device__ float g_as2[MAXN];
__device__ float g_ad2[MAXN];
__device__ int g_rank[MAXE];
__device__ int g_csrc[MAXE];
__device__ int g_rowptr[MAXN + 1];
__device__ int g_cnt[MAXN];
__device__ int g_bsum[72];
__device__ int g_is64;

// ---------------- helpers ----------------
__device__ __forceinline__ float4 h4f4(uint2 u) {
    half2 a = *reinterpret_cast<half2*>(&u.x);
    half2 b = *reinterpret_cast<half2*>(&u.y);
    float2 fa = __half22float2(a), fb = __half22float2(b);
    float4 r; r.x = fa.x; r.y = fa.y; r.z = fb.x; r.w = fb.y; return r;
}
__device__ __forceinline__ uint2 f4h4(float4 v) {
    half2 a = __floats2half2_rn(v.x, v.y);
    half2 b = __floats2half2_rn(v.z, v.w);
    uint2 u;
    u.x = *reinterpret_cast<unsigned*>(&a);
    u.y = *reinterpret_cast<unsigned*>(&b);
    return u;
}
__device__ __forceinline__ float dot4(float4 a, float4 b) {
    return a.x * b.x + a.y * b.y + a.z * b.z + a.w * b.w;
}

// ---------------- dtype sniff (R7 form; early-breaks fast on int32) ----------------
__global__ void detect_kernel(const unsigned int* __restrict__ raw, int E) {
    if (threadIdx.x != 0 || blockIdx.x != 0) return;
    int step = E / 64; if (step < 1) step = 1;
    int allz = 1;
    for (int k = 0; k < 64; k++) {
        long long j = 2LL * (long long)k * step + 1;
        if (j >= 2LL * E) break;
        if (raw[j] != 0u) { allz = 0; break; }
    }
    g_is64 = allz;
}

// ---------------- histogram + per-edge rank (8 edges/thread) ----------------
__global__ void convert_idx_kernel(const void* __restrict__ raw, int* __restrict__ rank,
                                   int* __restrict__ cnt, int E) {
    int i0 = (blockIdx.x * blockDim.x + threadIdx.x) * 8;
    if (i0 >= E) return;
    int m = min(8, E - i0);
    int dv[8];
    if (g_is64) {
        const int2* p = (const int2*)raw;
        #pragma unroll
        for (int k = 0; k < 8; k++) if (k < m) dv[k] = p[E + i0 + k].x;
    } else {
        const int* p = (const int*)raw;
        #pragma unroll
        for (int k = 0; k < 8; k++) if (k < m) dv[k] = p[E + i0 + k];
    }
    #pragma unroll
    for (int k = 0; k < 8; k++) if (k < m) rank[i0 + k] = atomicAdd(&cnt[dv[k]], 1);
}

// ---------------- multi-block exclusive scan (3 phases) ----------------
// scan1: per-block Hillis-Steele over 1024 elems; rowptr gets block-local exclusive,
//        bsum[b] gets the block total.
__global__ void scan1_kernel(const int* __restrict__ cnt, int* __restrict__ rowptr,
                             int* __restrict__ bsum, int n) {
    __shared__ int sm[1024];
    int t = threadIdx.x;
    int i = blockIdx.x * 1024 + t;
    int v = (i < n) ? cnt[i] : 0;
    sm[t] = v;
    __syncthreads();
    #pragma unroll
    for (int off = 1; off < 1024; off <<= 1) {
        int x = (t >= off) ? sm[t - off] : 0;
        __syncthreads();
        sm[t] += x;
        __syncthreads();
    }
    if (i < n) rowptr[i] = sm[t] - v;
    if (t == 1023) bsum[blockIdx.x] = sm[1023];
}

// scan2: exclusive scan of <=64 block totals (one tiny block)
__global__ void scan2_kernel(int* __restrict__ bsum, int nb) {
    __shared__ int sm[64];
    int t = threadIdx.x;
    int v = (t < nb) ? bsum[t] : 0;
    sm[t] = v;
    __syncthreads();
    #pragma unroll
    for (int off = 1; off < 64; off <<= 1) {
        int x = (t >= off) ? sm[t - off] : 0;
        __syncthreads();
        sm[t] += x;
        __syncthreads();
    }
    if (t < nb) bsum[t] = sm[t] - v;
}

// scan3: add block offsets; rowptr[n] = E (total known a priori)
__global__ void scan3_kernel(int* __restrict__ rowptr, const int* __restrict__ bsum,
                             int n, int E) {
    int i = blockIdx.x * blockDim.x + threadIdx.x;
    if (i < n) rowptr[i] += bsum[i >> 10];
    if (i == 0) rowptr[n] = E;
}

// ---------------- CSR fill: pure scatter, 8 edges/thread ----------------
__global__ void fill_kernel(const void* __restrict__ raw, const int* __restrict__ rank,
                            const int* __restrict__ rowptr, int* __restrict__ csrc, int E) {
    int i0 = (blockIdx.x * blockDim.x + threadIdx.x) * 8;
    if (i0 >= E) return;
    int m = min(8, E - i0);
    int sv[8], dv[8], rv[8], rp[8];
    if (g_is64) {
        const int2* p = (const int2*)raw;
        #pragma unroll
        for (int k = 0; k < 8; k++) if (k < m) { sv[k] = p[i0 + k].x; dv[k] = p[E + i0 + k].x; }
    } else {
        const int* p = (const int*)raw;
        #pragma unroll
        for (int k = 0; k < 8; k++) if (k < m) { sv[k] = p[i0 + k]; dv[k] = p[E + i0 + k]; }
    }
    #pragma unroll
    for (int k = 0; k < 8; k++) if (k < m) rv[k] = rank[i0 + k];
    #pragma unroll
    for (int k = 0; k < 8; k++) if (k < m) rp[k] = rowptr[dv[k]];
    #pragma unroll
    for (int k = 0; k < 8; k++) if (k < m) csrc[rp[k] + rv[k]] = sv[k];
}

// ---------------- prep: W -> fp16, fused logit vectors v = W^T a ----------------
__global__ void prep_kernel(const float* __restrict__ W1, const float* __restrict__ W2,
                            const float* __restrict__ a1s, const float* __restrict__ a1d,
                            const float* __restrict__ a2s, const float* __restrict__ a2d,
                            __half* __restrict__ W1h, __half* __restrict__ W2h,
                            float* __restrict__ val) {
    int t = threadIdx.x;
    for (int i = t; i < DIM * DIM; i += 256) {
        W1h[i] = __float2half(W1[i]);
        W2h[i] = __float2half(W2[i]);
    }
    if (t < 128) {
        int k = t;
        float s0 = 0.f, s1 = 0.f, d0 = 0.f, d1 = 0.f;
        for (int c = 0; c < 64; c++) {
            float w0 = W1[c * DIM + k], w1 = W1[(64 + c) * DIM + k];
            s0 += a1s[c] * w0;      s1 += a1s[64 + c] * w1;
            d0 += a1d[c] * w0;      d1 += a1d[64 + c] * w1;
        }
        val[k] = s0; val[128 + k] = s1; val[256 + k] = d0; val[384 + k] = d1;
        float us = 0.f, ud = 0.f;
        for (int o = 0; o < 128; o++) {
            float w = W2[o * DIM + k];
            us += a2s[o] * w; ud += a2d[o] * w;
        }
        val[512 + k] = us; val[640 + k] = ud;
    }
}

// ---------------- x -> fp16 + layer-1 logits (exact fp32 math) ----------------
__global__ void xconv_kernel(const float4* __restrict__ x, const float* __restrict__ val,
                             uint2* __restrict__ xh, float* __restrict__ as1,
                             float* __restrict__ ad1, int n) {
    int g = blockIdx.x * blockDim.x + threadIdx.x;
    int node = g >> 5, lane = g & 31;
    if (node >= n) return;
    float4 xv = x[node * 32 + lane];
    xh[node * 32 + lane] = f4h4(xv);
    float4 vs0 = ((const float4*)val)[lane];
    float4 vs1 = ((const float4*)(val + 128))[lane];
    float4 vd0 = ((const float4*)(val + 256))[lane];
    float4 vd1 = ((const float4*)(val + 384))[lane];
    float s0 = dot4(xv, vs0), s1 = dot4(xv, vs1);
    float d0 = dot4(xv, vd0), d1 = dot4(xv, vd1);
    #pragma unroll
    for (int off = 16; off >= 1; off >>= 1) {
        s0 += __shfl_xor_sync(0xffffffff, s0, off);
        s1 += __shfl_xor_sync(0xffffffff, s1, off);
        d0 += __shfl_xor_sync(0xffffffff, d0, off);
        d1 += __shfl_xor_sync(0xffffffff, d1, off);
    }
    if (lane == 0) {
        as1[node * 2] = s0; as1[node * 2 + 1] = s1;
        ad1[node * 2] = d0; ad1[node * 2 + 1] = d1;
    }
}

// ---------------- fp16 WMMA GEMM: C[m][o] = sum_k A[m][k] * W[o][k] ----------------
__global__ void hgemm_kernel(const __half* __restrict__ A, const __half* __restrict__ W,
                             __half* __restrict__ C, int nrows) {
    extern __shared__ __half smh[];
    __half* As = smh;              // [128][136]
    __half* Bs = smh + 128 * 136;  // [128][136]
    int tid = threadIdx.x;
    int row0 = blockIdx.x * 128;

    #pragma unroll
    for (int i = 0; i < 16; i++) {
        int idx = tid + i * 256;
        int r = idx >> 5, c4 = idx & 31;
        uint2 v = {0u, 0u};
        if (row0 + r < nrows) v = ((const uint2*)A)[(size_t)(row0 + r) * 32 + c4];
        *(uint2*)&As[r * 136 + c4 * 4] = v;
    }
    #pragma unroll
    for (int i = 0; i < 16; i++) {
        int idx = tid + i * 256;
        int r = idx >> 5, c4 = idx & 31;
        *(uint2*)&Bs[r * 136 + c4 * 4] = ((const uint2*)W)[idx];
    }
    __syncthreads();

    int wid = tid >> 5;
    int wm = wid >> 1, wn = wid & 1;

    wmma::fragment<wmma::accumulator, 16, 16, 16, float> acc[2][4];
    #pragma unroll
    for (int i = 0; i < 2; i++)
        #pragma unroll
        for (int j = 0; j < 4; j++) wmma::fill_fragment(acc[i][j], 0.f);

    #pragma unroll
    for (int ks = 0; ks < 8; ks++) {
        wmma::fragment<wmma::matrix_a, 16, 16, 16, __half, wmma::row_major> af[2];
        #pragma unroll
        for (int i = 0; i < 2; i++)
            wmma::load_matrix_sync(af[i], &As[(wm * 32 + i * 16) * 136 + ks * 16], 136);
        wmma::fragment<wmma::matrix_b, 16, 16, 16, __half, wmma::col_major> bf[4];
        #pragma unroll
        for (int j = 0; j < 4; j++)
            wmma::load_matrix_sync(bf[j], &Bs[(wn * 64 + j * 16) * 136 + ks * 16], 136);
        #pragma unroll
        for (int i = 0; i < 2; i++)
            #pragma unroll
            for (int j = 0; j < 4; j++)
                wmma::mma_sync(acc[i][j], af[i], bf[j], acc[i][j]);
    }

    #pragma unroll
    for (int i = 0; i < 2; i++)
        #pragma unroll
        for (int j = 0; j < 4; j++) {
            wmma::fragment<wmma::accumulator, 16, 16, 16, __half> hf;
            #pragma unroll
            for (int e = 0; e < hf.num_elements; e++) hf.x[e] = __float2half(acc[i][j].x[e]);
            wmma::store_matrix_sync(&C[(size_t)(row0 + wm * 32 + i * 16) * DIM + wn * 64 + j * 16],
                                    hf, DIM, wmma::mem_row_major);
        }
}

// ---------------- GAT gather (R7 winner shape): warp/dst node, x8 batched loads ----------------
template <int HEADS, bool RELU, bool ALPHA2>
__global__ void __launch_bounds__(256)
gat_gather_kernel(const int* __restrict__ rowptr, const int* __restrict__ csrc,
                  const uint2* __restrict__ h, const float* __restrict__ as_,
                  const float* __restrict__ ad_, const float* __restrict__ bias,
                  const float* __restrict__ val, uint2* __restrict__ outh,
                  float* __restrict__ as2, float* __restrict__ ad2, int n) {
    int g = blockIdx.x * blockDim.x + threadIdx.x;
    int d = g >> 5, lane = threadIdx.x & 31;
    if (d >= n) return;
    int head = (HEADS == 2) ? (lane >> 4) : 0;
    float adv = ad_[d * HEADS + head];

    float4 acc;
    float den;
    {   // self loop
        float a = as_[d * HEADS + head] + adv;
        float lr = (a > 0.f) ? a : 0.2f * a;
        float w = __expf(lr);
        float4 hv = h4f4(h[d * 32 + lane]);
        acc.x = w * hv.x; acc.y = w * hv.y; acc.z = w * hv.z; acc.w = w * hv.w;
        den = w;
    }

    int e0 = rowptr[d], e1 = rowptr[d + 1];
    int e = e0;
    for (; e + 8 <= e1; e += 8) {
        int s[8];
        #pragma unroll
        for (int k = 0; k < 8; k++) s[k] = csrc[e + k];
        float a[8];
        #pragma unroll
        for (int k = 0; k < 8; k++) a[k] = as_[s[k] * HEADS + head];
        uint2 u[8];
        #pragma unroll
        for (int k = 0; k < 8; k++) u[k] = h[s[k] * 32 + lane];
        #pragma unroll
        for (int k = 0; k < 8; k++) {
            float t = a[k] + adv;
            t = (t > 0.f) ? t : 0.2f * t;
            float w = __expf(t);
            float4 hv = h4f4(u[k]);
            acc.x += w * hv.x; acc.y += w * hv.y;
            acc.z += w * hv.z; acc.w += w * hv.w;
            den += w;
        }
    }
    for (; e < e1; e++) {
        int s = csrc[e];
        float a = as_[s * HEADS + head] + adv;
        float lr = (a > 0.f) ? a : 0.2f * a;
        float w = __expf(lr);
        float4 hv = h4f4(h[s * 32 + lane]);
        acc.x += w * hv.x; acc.y += w * hv.y; acc.z += w * hv.z; acc.w += w * hv.w;
        den += w;
    }

    float inv = 1.f / den;
    float4 b = ((const float4*)bias)[lane];
    float4 r;
    r.x = acc.x * inv + b.x; r.y = acc.y * inv + b.y;
    r.z = acc.z * inv + b.z; r.w = acc.w * inv + b.w;
    if (RELU) {
        r.x = fmaxf(r.x, 0.f); r.y = fmaxf(r.y, 0.f);
        r.z = fmaxf(r.z, 0.f); r.w = fmaxf(r.w, 0.f);
    }
    outh[d * 32 + lane] = f4h4(r);

    if (ALPHA2) {
        float4 us = ((const float4*)(val + 512))[lane];
        float4 ud = ((const float4*)(val + 640))[lane];
        float ss = dot4(r, us), dd = dot4(r, ud);
        #pragma unroll
        for (int off = 16; off >= 1; off >>= 1) {
            ss += __shfl_xor_sync(0xffffffff, ss, off);
            dd += __shfl_xor_sync(0xffffffff, dd, off);
        }
        if (lane == 0) { as2[d] = ss; ad2[d] = dd; }
    }
}

// ---------------- mean conv gather (R7 shape) + residual + relu ----------------
__global__ void __launch_bounds__(256)
mean_gather_kernel(const int* __restrict__ rowptr, const int* __restrict__ csrc,
                   const uint2* __restrict__ h, const float4* __restrict__ x,
                   float4* __restrict__ out, int n) {
    int g = blockIdx.x * blockDim.x + threadIdx.x;
    int d = g >> 5, lane = threadIdx.x & 31;
    if (d >= n) return;
    int e0 = rowptr[d], e1 = rowptr[d + 1];
    float4 acc = {0.f, 0.f, 0.f, 0.f};
    int e = e0;
    for (; e + 8 <= e1; e += 8) {
        int s[8];
        #pragma unroll
        for (int k = 0; k < 8; k++) s[k] = csrc[e + k];
        uint2 u[8];
        #pragma unroll
        for (int k = 0; k < 8; k++) u[k] = h[s[k] * 32 + lane];
        #pragma unroll
        for (int k = 0; k < 8; k++) {
            float4 hv = h4f4(u[k]);
            acc.x += hv.x; acc.y += hv.y; acc.z += hv.z; acc.w += hv.w;
        }
    }
    for (; e < e1; e++) {
        float4 hv = h4f4(h[csrc[e] * 32 + lane]);
        acc.x += hv.x; acc.y += hv.y; acc.z += hv.z; acc.w += hv.w;
    }
    int cnt = e1 - e0;
    float inv = (cnt > 0) ? (1.f / (float)cnt) : 0.f;
    float4 xv = x[d * 32 + lane];
    float4 r;
    r.x = fmaxf(acc.x * inv + xv.x, 0.f);
    r.y = fmaxf(acc.y * inv + xv.y, 0.f);
    r.z = fmaxf(acc.z * inv + xv.z, 0.f);
    r.w = fmaxf(acc.w * inv + xv.w, 0.f);
    out[d * 32 + lane] = r;
}

// ---------------- launch ----------------
extern "C" void kernel_launch(void* const* d_in, const int* in_sizes, int n_in,
                              void* d_out, int out_size) {
    const float* x    = (const float*)d_in[0];
    const void*  ei   = d_in[1];
    const float* W1   = (const float*)d_in[2];
    const float* asv1 = (const float*)d_in[3];
    const float* adv1 = (const float*)d_in[4];
    const float* b1   = (const float*)d_in[5];
    const float* W2   = (const float*)d_in[6];
    const float* asv2 = (const float*)d_in[7];
    const float* adv2 = (const float*)d_in[8];
    const float* b2   = (const float*)d_in[9];
    float* out = (float*)d_out;

    int n = in_sizes[0] / DIM;
    int E = in_sizes[1] / 2;

    uint2 *xh, *h1, *h2, *h3, *h4;
    __half *W1h, *W2h;
    float *val, *as1, *ad1, *as2, *ad2;
    int *rank, *csrc, *rowptr, *cnt, *bsum;
    cudaGetSymbolAddress((void**)&xh,     g_xh);
    cudaGetSymbolAddress((void**)&h1,     g_h1);
    cudaGetSymbolAddress((void**)&h2,     g_h2);
    cudaGetSymbolAddress((void**)&h3,     g_h3);
    cudaGetSymbolAddress((void**)&h4,     g_h4);
    cudaGetSymbolAddress((void**)&W1h,    g_W1h);
    cudaGetSymbolAddress((void**)&W2h,    g_W2h);
    cudaGetSymbolAddress((void**)&val,    g_val);
    cudaGetSymbolAddress((void**)&as1,    g_as1);
    cudaGetSymbolAddress((void**)&ad1,    g_ad1);
    cudaGetSymbolAddress((void**)&as2,    g_as2);
    cudaGetSymbolAddress((void**)&ad2,    g_ad2);
    cudaGetSymbolAddress((void**)&rank,   g_rank);
    cudaGetSymbolAddress((void**)&csrc,   g_csrc);
    cudaGetSymbolAddress((void**)&rowptr, g_rowptr);
    cudaGetSymbolAddress((void**)&cnt,    g_cnt);
    cudaGetSymbolAddress((void**)&bsum,   g_bsum);

    const int hgemm_smem = 2 * 128 * 136 * (int)sizeof(__half);
    cudaFuncSetAttribute(hgemm_kernel, cudaFuncAttributeMaxDynamicSharedMemorySize, hgemm_smem);

    int gemm_blocks  = (n + 127) / 128;
    int nwarp_blocks = (n * 32 + 255) / 256;
    int e8_blocks    = ((E + 7) / 8 + 255) / 256;
    int nb           = (n + 1023) / 1024;   // 49 for n=50000 (<=64 supported)

    // ---- fork: CSR build on side stream, feature prep on main stream (R7 layout) ----
    cudaStream_t s;
    cudaStreamCreateWithFlags(&s, cudaStreamNonBlocking);
    cudaEvent_t evFork, evJoin;
    cudaEventCreateWithFlags(&evFork, cudaEventDisableTiming);
    cudaEventCreateWithFlags(&evJoin, cudaEventDisableTiming);

    cudaEventRecord(evFork, 0);
    cudaStreamWaitEvent(s, evFork, 0);

    // side stream: CSR build (by destination) with multi-block scan
    cudaMemsetAsync(cnt, 0, (size_t)n * sizeof(int), s);
    detect_kernel<<<1, 64, 0, s>>>((const unsigned int*)ei, E);
    convert_idx_kernel<<<e8_blocks, 256, 0, s>>>(ei, rank, cnt, E);
    scan1_kernel<<<nb, 1024, 0, s>>>(cnt, rowptr, bsum, n);
    scan2_kernel<<<1, 64, 0, s>>>(bsum, nb);
    scan3_kernel<<<(n + 1023) / 1024, 1024, 0, s>>>(rowptr, bsum, n, E);
    fill_kernel<<<e8_blocks, 256, 0, s>>>(ei, rank, rowptr, csrc, E);
    cudaEventRecord(evJoin, s);

    // main stream: prep + x conversion + GEMM1 (no CSR dependency)
    prep_kernel<<<1, 256>>>(W1, W2, asv1, adv1, asv2, adv2, W1h, W2h, val);
    xconv_kernel<<<nwarp_blocks, 256>>>((const float4*)x, val, xh, as1, ad1, n);
    hgemm_kernel<<<gemm_blocks, 256, hgemm_smem>>>((const __half*)xh, W1h, (__half*)h1, n);

    // join: gather-1 needs both CSR and h1
    cudaStreamWaitEvent(0, evJoin, 0);

    gat_gather_kernel<2, true, true><<<nwarp_blocks, 256>>>(rowptr, csrc, h1, as1, ad1, b1,
                                                            val, h2, as2, ad2, n);

    hgemm_kernel<<<gemm_blocks, 256, hgemm_smem>>>((const __half*)h2, W2h, (__half*)h3, n);
    gat_gather_kernel<1, false, false><<<nwarp_blocks, 256>>>(rowptr, csrc, h3, as2, ad2, b2,
                                                              val, h4, nullptr, nullptr, n);

    mean_gather_kernel<<<nwarp_blocks, 256>>>(rowptr, csrc, h4, (const float4*)x,
                                              (float4*)out, n);
    // note: stream/events intentionally not destroyed during potential capture
}